// round 2
// baseline (speedup 1.0000x reference)
#include <cuda_runtime.h>
#include <math.h>
#include <stdint.h>

// Problem constants
#define B_    16
#define HH    56
#define WW_   56
#define C_    512
#define NH_   16
#define WS_   7
#define SS_   3
#define NTOK  49            // WS*WS
#define NWIN  64            // (56/7)^2
#define HD_   32
#define MLPH  2048
#define MROWS 50176         // B * NWIN * NTOK  == B * H * W
#define SCALE_ 0.17677669529663687f

// ---------------- scratch (device globals; no allocation allowed) ------------
__device__ float g_a1w [(size_t)MROWS * 512];   // LN1'd, rolled, windowed x1
__device__ float g_qkv [(size_t)MROWS * 1536];  // qkv activations
__device__ float g_attn[(size_t)MROWS * 512];   // attention output (windowed)
__device__ float g_x   [(size_t)MROWS * 512];   // residual stream after proj
__device__ float g_ln2 [(size_t)MROWS * 512];   // LN2 output
__device__ float g_h1  [(size_t)MROWS * 2048];  // fc1+gelu output

// ---------------- LayerNorm kernels ------------------------------------------
// MODE 0: plain LN row m of src -> dst row m
// MODE 1: LN of x1 with roll(-3,-3) + window partition fused:
//         output window-row m reads source pixel at rolled position.
template <int MODE>
__global__ __launch_bounds__(128)
void ln_kernel(const float* __restrict__ src, const float* __restrict__ g,
               const float* __restrict__ b, float* __restrict__ dst)
{
    const int m = blockIdx.x;
    const float* row;
    if (MODE == 1) {
        int r  = m / NTOK, nt = m % NTOK;
        int bb = r >> 6,   wi = r & 63;
        int wh = wi >> 3,  ww = wi & 7;
        int ih = nt / 7,   iw = nt % 7;
        int hs = wh * 7 + ih + SS_; if (hs >= HH)  hs -= HH;
        int ws = ww * 7 + iw + SS_; if (ws >= WW_) ws -= WW_;
        row = src + ((size_t)bb * 3136 + hs * 56 + ws) * 512;
    } else {
        row = src + (size_t)m * 512;
    }
    const int t = threadIdx.x;
    float4 v = *(const float4*)(row + t * 4);
    float s = v.x + v.y + v.z + v.w;
    float q = v.x * v.x + v.y * v.y + v.z * v.z + v.w * v.w;
    #pragma unroll
    for (int o = 16; o; o >>= 1) {
        s += __shfl_xor_sync(0xffffffffu, s, o);
        q += __shfl_xor_sync(0xffffffffu, q, o);
    }
    __shared__ float red[8];
    int warp = t >> 5, lane = t & 31;
    if (lane == 0) { red[warp] = s; red[warp + 4] = q; }
    __syncthreads();
    s = red[0] + red[1] + red[2] + red[3];
    q = red[4] + red[5] + red[6] + red[7];
    float mean = s * (1.0f / 512.0f);
    float var  = q * (1.0f / 512.0f) - mean * mean;
    float rstd = rsqrtf(var + 1e-5f);
    float4 gv = *(const float4*)(g + t * 4);
    float4 bv = *(const float4*)(b + t * 4);
    float4 o4;
    o4.x = (v.x - mean) * rstd * gv.x + bv.x;
    o4.y = (v.y - mean) * rstd * gv.y + bv.y;
    o4.z = (v.z - mean) * rstd * gv.z + bv.z;
    o4.w = (v.w - mean) * rstd * gv.w + bv.w;
    *(float4*)(dst + (size_t)m * 512 + t * 4) = o4;
}

// ---------------- Tiled fp32 NT GEMM with fused epilogues ---------------------
// C[m,n] = sum_k A[m,k] * B[n,k] + bias[n], then per-EPI transform.
#define BM 128
#define BN 128
#define BK 16

enum { EPI_NONE = 0, EPI_GELU = 1, EPI_SCATTER = 2, EPI_RES = 3 };

template <int EPI>
__global__ __launch_bounds__(256, 2)
void gemm_nt(const float* __restrict__ A, const float* __restrict__ Bw,
             const float* __restrict__ bias, float* __restrict__ C,
             const float* __restrict__ res, int M, int N, int K)
{
    __shared__ float As[BK][BM];
    __shared__ float Bs[BK][BN];

    const int tid = threadIdx.x;
    const int m0 = blockIdx.y * BM;
    const int n0 = blockIdx.x * BN;

    const int lr = tid >> 2;          // 0..63 : row within tile (two passes)
    const int lc = (tid & 3) << 2;    // 0,4,8,12 : k offset
    const int ty = tid >> 4;          // 0..15
    const int tx = tid & 15;          // 0..15

    float acc[8][8];
    #pragma unroll
    for (int i = 0; i < 8; i++)
        #pragma unroll
        for (int j = 0; j < 8; j++) acc[i][j] = 0.0f;

    const float* Aptr = A  + (size_t)m0 * K;
    const float* Bptr = Bw + (size_t)n0 * K;

    for (int k0 = 0; k0 < K; k0 += BK) {
        #pragma unroll
        for (int p = 0; p < 2; p++) {
            int row = lr + p * 64;
            float4 v = *(const float4*)(Aptr + (size_t)row * K + k0 + lc);
            As[lc + 0][row] = v.x; As[lc + 1][row] = v.y;
            As[lc + 2][row] = v.z; As[lc + 3][row] = v.w;
        }
        #pragma unroll
        for (int p = 0; p < 2; p++) {
            int row = lr + p * 64;
            float4 v = *(const float4*)(Bptr + (size_t)row * K + k0 + lc);
            Bs[lc + 0][row] = v.x; Bs[lc + 1][row] = v.y;
            Bs[lc + 2][row] = v.z; Bs[lc + 3][row] = v.w;
        }
        __syncthreads();
        #pragma unroll
        for (int k = 0; k < BK; k++) {
            float4 a0 = *(const float4*)&As[k][ty * 8 + 0];
            float4 a1 = *(const float4*)&As[k][ty * 8 + 4];
            float4 b0 = *(const float4*)&Bs[k][tx * 8 + 0];
            float4 b1 = *(const float4*)&Bs[k][tx * 8 + 4];
            float ra[8] = {a0.x, a0.y, a0.z, a0.w, a1.x, a1.y, a1.z, a1.w};
            float rb[8] = {b0.x, b0.y, b0.z, b0.w, b1.x, b1.y, b1.z, b1.w};
            #pragma unroll
            for (int i = 0; i < 8; i++)
                #pragma unroll
                for (int j = 0; j < 8; j++)
                    acc[i][j] = fmaf(ra[i], rb[j], acc[i][j]);
        }
        __syncthreads();
    }

    #pragma unroll
    for (int i = 0; i < 8; i++) {
        int m = m0 + ty * 8 + i;
        size_t orow;
        if (EPI == EPI_SCATTER) {
            // window row m -> final (b,h,w) position (reverse partition + roll +3)
            int r  = m / NTOK, nt = m % NTOK;
            int bb = r >> 6,   wi = r & 63;
            int wh = wi >> 3,  ww = wi & 7;
            int ih = nt / 7,   iw = nt % 7;
            int h = wh * 7 + ih + SS_; if (h >= HH)  h -= HH;
            int w = ww * 7 + iw + SS_; if (w >= WW_) w -= WW_;
            orow = (size_t)bb * 3136 + h * 56 + w;
        } else {
            orow = (size_t)m;
        }
        #pragma unroll
        for (int j = 0; j < 8; j++) {
            int n = n0 + tx * 8 + j;
            float v = acc[i][j] + bias[n];
            if (EPI == EPI_GELU) {
                v = 0.5f * v * (1.0f + erff(v * 0.70710678118654752f));
                C[(size_t)m * N + n] = v;
            } else if (EPI == EPI_SCATTER) {
                C[orow * N + n] = v + res[orow * N + n];
            } else if (EPI == EPI_RES) {
                C[(size_t)m * N + n] = v + res[(size_t)m * N + n];
            } else {
                C[(size_t)m * N + n] = v;
            }
        }
    }
}

// ---------------- Windowed attention (one block per (window, head)) -----------
__global__ __launch_bounds__(128)
void attn_kernel(const float* __restrict__ qkv, const float* __restrict__ rel_tab,
                 float* __restrict__ out)
{
    __shared__ float Qs[NTOK][33], Ks[NTOK][33], Vs[NTOK][33];
    __shared__ float S[NTOK * NTOK];

    const int bi = blockIdx.x;
    const int h  = bi & 15;
    const int r  = bi >> 4;
    const int wi = r & 63;
    const int tid = threadIdx.x;

    const float* base = qkv + (size_t)r * NTOK * 1536 + h * 32;
    for (int e = tid; e < NTOK * 32; e += 128) {
        int n = e >> 5, d = e & 31;
        Qs[n][d] = base[n * 1536 + d] * SCALE_;
        Ks[n][d] = base[n * 1536 + 512 + d];
        Vs[n][d] = base[n * 1536 + 1024 + d];
    }
    __syncthreads();

    const int wh = wi >> 3, ww = wi & 7;
    for (int e = tid; e < NTOK * NTOK; e += 128) {
        int i = e / NTOK, j = e % NTOK;
        float s = 0.0f;
        #pragma unroll
        for (int d = 0; d < 32; d++) s = fmaf(Qs[i][d], Ks[j][d], s);
        int ih = i / 7, iw = i % 7, jh = j / 7, jw = j % 7;
        int ridx = (ih - jh + 6) * 13 + (iw - jw + 6);
        s += rel_tab[ridx * NH_ + h];
        // shifted-window attention mask (regions of rolled image)
        int hi = wh * 7 + ih, wgi = ww * 7 + iw;
        int hj = wh * 7 + jh, wgj = ww * 7 + jw;
        int li = ((hi < 49) ? 0 : (hi < 53) ? 1 : 2) * 3 + ((wgi < 49) ? 0 : (wgi < 53) ? 1 : 2);
        int lj = ((hj < 49) ? 0 : (hj < 53) ? 1 : 2) * 3 + ((wgj < 49) ? 0 : (wgj < 53) ? 1 : 2);
        if (li != lj) s -= 100.0f;
        S[e] = s;
    }
    __syncthreads();

    // softmax: one warp per row
    const int warp = tid >> 5, lane = tid & 31;
    for (int i = warp; i < NTOK; i += 4) {
        float mx = -1e30f;
        for (int j = lane; j < NTOK; j += 32) mx = fmaxf(mx, S[i * NTOK + j]);
        #pragma unroll
        for (int o = 16; o; o >>= 1) mx = fmaxf(mx, __shfl_xor_sync(0xffffffffu, mx, o));
        float sum = 0.0f;
        for (int j = lane; j < NTOK; j += 32) {
            float p = expf(S[i * NTOK + j] - mx);
            S[i * NTOK + j] = p;
            sum += p;
        }
        #pragma unroll
        for (int o = 16; o; o >>= 1) sum += __shfl_xor_sync(0xffffffffu, sum, o);
        float inv = 1.0f / sum;
        for (int j = lane; j < NTOK; j += 32) S[i * NTOK + j] *= inv;
    }
    __syncthreads();

    float* obase = out + (size_t)r * NTOK * 512 + h * 32;
    for (int e = tid; e < NTOK * 32; e += 128) {
        int i = e >> 5, d = e & 31;
        float acc = 0.0f;
        #pragma unroll
        for (int j = 0; j < NTOK; j++) acc = fmaf(S[i * NTOK + j], Vs[j][d], acc);
        obase[i * 512 + d] = acc;
    }
}

// ---------------- launcher ----------------------------------------------------
extern "C" void kernel_launch(void* const* d_in, const int* in_sizes, int n_in,
                              void* d_out, int out_size)
{
    const float* x1      = (const float*)d_in[0];
    // d_in[1] = x2 : provably dead (output keeps only attn1/v1 head channels)
    const float* norm1_g = (const float*)d_in[2];
    const float* norm1_b = (const float*)d_in[3];
    const float* qkv_w   = (const float*)d_in[4];
    const float* qkv_b   = (const float*)d_in[5];
    const float* rel_tab = (const float*)d_in[6];
    const float* proj_w  = (const float*)d_in[7];
    const float* proj_b  = (const float*)d_in[8];
    const float* norm2_g = (const float*)d_in[9];
    const float* norm2_b = (const float*)d_in[10];
    const float* fc1_w   = (const float*)d_in[11];
    const float* fc1_b   = (const float*)d_in[12];
    const float* fc2_w   = (const float*)d_in[13];
    const float* fc2_b   = (const float*)d_in[14];

    float *a1w, *qkvb, *attnb, *xb, *ln2b, *h1b;
    cudaGetSymbolAddress((void**)&a1w,   g_a1w);
    cudaGetSymbolAddress((void**)&qkvb,  g_qkv);
    cudaGetSymbolAddress((void**)&attnb, g_attn);
    cudaGetSymbolAddress((void**)&xb,    g_x);
    cudaGetSymbolAddress((void**)&ln2b,  g_ln2);
    cudaGetSymbolAddress((void**)&h1b,   g_h1);

    // 1) LN1 + roll(-3,-3) + window partition
    ln_kernel<1><<<MROWS, 128>>>(x1, norm1_g, norm1_b, a1w);

    // 2) QKV projection: [M,512] @ [1536,512]^T
    {
        dim3 grid(1536 / BN, MROWS / BM);
        gemm_nt<EPI_NONE><<<grid, 256>>>(a1w, qkv_w, qkv_b, qkvb, nullptr,
                                         MROWS, 1536, 512);
    }

    // 3) windowed attention (bias + mask + softmax + @V)
    attn_kernel<<<B_ * NWIN * NH_, 128>>>(qkvb, rel_tab, attnb);

    // 4) proj + reverse-partition + roll(+3,+3) + residual(x1)
    {
        dim3 grid(512 / BN, MROWS / BM);
        gemm_nt<EPI_SCATTER><<<grid, 256>>>(attnb, proj_w, proj_b, xb, x1,
                                            MROWS, 512, 512);
    }

    // 5) LN2
    ln_kernel<0><<<MROWS, 128>>>(xb, norm2_g, norm2_b, ln2b);

    // 6) fc1 + exact GELU
    {
        dim3 grid(2048 / BN, MROWS / BM);
        gemm_nt<EPI_GELU><<<grid, 256>>>(ln2b, fc1_w, fc1_b, h1b, nullptr,
                                         MROWS, 2048, 512);
    }

    // 7) fc2 + residual -> out
    {
        dim3 grid(512 / BN, MROWS / BM);
        gemm_nt<EPI_RES><<<grid, 256>>>(h1b, fc2_w, fc2_b, (float*)d_out, xb,
                                        MROWS, 512, 2048);
    }
}

// round 4
// speedup vs baseline: 3.5967x; 3.5967x over previous
#include <cuda_runtime.h>
#include <math.h>
#include <stdint.h>

// Problem constants
#define B_    16
#define HH    56
#define WW_   56
#define C_    512
#define NH_   16
#define WS_   7
#define SS_   3
#define NTOK  49
#define NWIN  64
#define HD_   32
#define MLPH  2048
#define MROWS 50176
#define SCALE_ 0.17677669529663687f

// ---------------- scratch ----------------------------------------------------
__device__ float g_a1w [(size_t)MROWS * 512];
__device__ float g_qkv [(size_t)MROWS * 1536];
__device__ float g_attn[(size_t)MROWS * 512];
__device__ float g_x   [(size_t)MROWS * 512];
__device__ float g_ln2 [(size_t)MROWS * 512];
__device__ float g_h1  [(size_t)MROWS * 2048];

// ---------------- LayerNorm ---------------------------------------------------
template <int MODE>
__global__ __launch_bounds__(128)
void ln_kernel(const float* __restrict__ src, const float* __restrict__ g,
               const float* __restrict__ b, float* __restrict__ dst)
{
    const int m = blockIdx.x;
    const float* row;
    if (MODE == 1) {
        int r  = m / NTOK, nt = m % NTOK;
        int bb = r >> 6,   wi = r & 63;
        int wh = wi >> 3,  ww = wi & 7;
        int ih = nt / 7,   iw = nt % 7;
        int hs = wh * 7 + ih + SS_; if (hs >= HH)  hs -= HH;
        int ws = ww * 7 + iw + SS_; if (ws >= WW_) ws -= WW_;
        row = src + ((size_t)bb * 3136 + hs * 56 + ws) * 512;
    } else {
        row = src + (size_t)m * 512;
    }
    const int t = threadIdx.x;
    float4 v = *(const float4*)(row + t * 4);
    float s = v.x + v.y + v.z + v.w;
    float q = v.x * v.x + v.y * v.y + v.z * v.z + v.w * v.w;
    #pragma unroll
    for (int o = 16; o; o >>= 1) {
        s += __shfl_xor_sync(0xffffffffu, s, o);
        q += __shfl_xor_sync(0xffffffffu, q, o);
    }
    __shared__ float red[8];
    int warp = t >> 5, lane = t & 31;
    if (lane == 0) { red[warp] = s; red[warp + 4] = q; }
    __syncthreads();
    s = red[0] + red[1] + red[2] + red[3];
    q = red[4] + red[5] + red[6] + red[7];
    float mean = s * (1.0f / 512.0f);
    float var  = q * (1.0f / 512.0f) - mean * mean;
    float rstd = rsqrtf(var + 1e-5f);
    float4 gv = *(const float4*)(g + t * 4);
    float4 bv = *(const float4*)(b + t * 4);
    float4 o4;
    o4.x = (v.x - mean) * rstd * gv.x + bv.x;
    o4.y = (v.y - mean) * rstd * gv.y + bv.y;
    o4.z = (v.z - mean) * rstd * gv.z + bv.z;
    o4.w = (v.w - mean) * rstd * gv.w + bv.w;
    *(float4*)(dst + (size_t)m * 512 + t * 4) = o4;
}

// ---------------- TF32 tensor-core GEMM --------------------------------------
// C[m,n] = sum_k A[m,k]*B[n,k] + bias[n]; epilogue variants.
enum { EPI_NONE = 0, EPI_GELU = 1, EPI_SCATTER = 2, EPI_RES = 3 };

#define LDT 36                 // padded row length (floats): bank = 4*row+col, conflict-free
#define ASZ (128 * LDT)        // one buffer, one matrix
#define SMEM_BYTES (4 * ASZ * 4)

__device__ __forceinline__ uint32_t f2tf(float x) {
    uint32_t r; asm("cvt.rna.tf32.f32 %0, %1;" : "=r"(r) : "f"(x)); return r;
}
__device__ __forceinline__ void mma8(float* c, const uint32_t* a, const uint32_t* b) {
    asm volatile(
        "mma.sync.aligned.m16n8k8.row.col.f32.tf32.tf32.f32 "
        "{%0,%1,%2,%3},{%4,%5,%6,%7},{%8,%9},{%0,%1,%2,%3};\n"
        : "+f"(c[0]), "+f"(c[1]), "+f"(c[2]), "+f"(c[3])
        : "r"(a[0]), "r"(a[1]), "r"(a[2]), "r"(a[3]), "r"(b[0]), "r"(b[1]));
}
__device__ __forceinline__ void cp16(uint32_t dst, const void* src) {
    asm volatile("cp.async.cg.shared.global [%0], [%1], 16;\n" :: "r"(dst), "l"(src));
}
__device__ __forceinline__ void cp_commit() { asm volatile("cp.async.commit_group;\n"); }
__device__ __forceinline__ void cp_wait0()  { asm volatile("cp.async.wait_group 0;\n"); }

__device__ __forceinline__ size_t scatter_row(int m) {
    int r  = m / NTOK, nt = m % NTOK;
    int bb = r >> 6,   wi = r & 63;
    int wh = wi >> 3,  ww = wi & 7;
    int ih = nt / 7,   iw = nt % 7;
    int h = wh * 7 + ih + SS_; if (h >= HH)  h -= HH;
    int w = ww * 7 + iw + SS_; if (w >= WW_) w -= WW_;
    return (size_t)bb * 3136 + h * 56 + w;
}

template <int EPI>
__global__ __launch_bounds__(256, 2)
void gemm_tc(const float* __restrict__ A, const float* __restrict__ Bw,
             const float* __restrict__ bias, float* __restrict__ C,
             const float* __restrict__ res, int M, int N, int K)
{
    extern __shared__ float sm[];
    const int tid  = threadIdx.x;
    const int lane = tid & 31, warp = tid >> 5;
    const int wm = warp & 1, wn = warp >> 1;     // 2 x 4 warp grid
    const int row = lane >> 2, col = lane & 3;
    const int m0 = blockIdx.y * 128, n0 = blockIdx.x * 128;

    float acc[4][4][4];
    #pragma unroll
    for (int i = 0; i < 4; i++)
        #pragma unroll
        for (int j = 0; j < 4; j++)
            #pragma unroll
            for (int t = 0; t < 4; t++) acc[i][j][t] = 0.0f;

    // loader mapping: each thread owns one row, 16 contiguous k-cols (4x float4)
    const int ldRow = tid >> 1;
    const int ldCol = (tid & 1) * 16;
    const float* aSrc = A  + (size_t)(m0 + ldRow) * K + ldCol;
    const float* bSrc = Bw + (size_t)(n0 + ldRow) * K + ldCol;
    const uint32_t smBase = (uint32_t)__cvta_generic_to_shared(sm);
    const uint32_t aDst = smBase + (uint32_t)(ldRow * LDT + ldCol) * 4;
    const uint32_t bDst = smBase + (uint32_t)(2 * ASZ + ldRow * LDT + ldCol) * 4;

    const int niter = K >> 5;   // BK = 32

    // prefetch tile 0 -> buffer 0
    #pragma unroll
    for (int p = 0; p < 4; p++) cp16(aDst + p * 16, aSrc + p * 4);
    #pragma unroll
    for (int p = 0; p < 4; p++) cp16(bDst + p * 16, bSrc + p * 4);
    cp_commit();

    int buf = 0;
    for (int it = 0; it < niter; it++) {
        cp_wait0();
        __syncthreads();

        if (it + 1 < niter) {
            const int nb = buf ^ 1;
            const float* as = aSrc + (it + 1) * 32;
            const float* bs = bSrc + (it + 1) * 32;
            const uint32_t ao = aDst + (uint32_t)(nb * ASZ) * 4;
            const uint32_t bo = bDst + (uint32_t)(nb * ASZ) * 4;
            #pragma unroll
            for (int p = 0; p < 4; p++) cp16(ao + p * 16, as + p * 4);
            #pragma unroll
            for (int p = 0; p < 4; p++) cp16(bo + p * 16, bs + p * 4);
            cp_commit();
        }

        const float* Ab = sm + buf * ASZ;
        const float* Bb = sm + 2 * ASZ + buf * ASZ;

        #pragma unroll
        for (int kk = 0; kk < 32; kk += 8) {
            uint32_t af[4][4], bf[4][2];
            #pragma unroll
            for (int im = 0; im < 4; im++) {
                const int mb = wm * 64 + im * 16 + row;
                af[im][0] = f2tf(Ab[(mb)     * LDT + kk + col]);
                af[im][1] = f2tf(Ab[(mb + 8) * LDT + kk + col]);
                af[im][2] = f2tf(Ab[(mb)     * LDT + kk + col + 4]);
                af[im][3] = f2tf(Ab[(mb + 8) * LDT + kk + col + 4]);
            }
            #pragma unroll
            for (int jn = 0; jn < 4; jn++) {
                const int nb2 = wn * 32 + jn * 8 + row;
                bf[jn][0] = f2tf(Bb[nb2 * LDT + kk + col]);
                bf[jn][1] = f2tf(Bb[nb2 * LDT + kk + col + 4]);
            }
            #pragma unroll
            for (int im = 0; im < 4; im++)
                #pragma unroll
                for (int jn = 0; jn < 4; jn++)
                    mma8(acc[im][jn], af[im], bf[jn]);
        }
        buf ^= 1;
    }

    // epilogue: each thread owns rows r0,r0+8 per im-tile, cols 2*col,2*col+1 per jn
    #pragma unroll
    for (int im = 0; im < 4; im++) {
        const int r0 = m0 + wm * 64 + im * 16 + row;
        const int r1 = r0 + 8;
        size_t o0, o1;
        if (EPI == EPI_SCATTER) { o0 = scatter_row(r0); o1 = scatter_row(r1); }
        else                    { o0 = (size_t)r0;      o1 = (size_t)r1; }
        #pragma unroll
        for (int jn = 0; jn < 4; jn++) {
            const int n = n0 + wn * 32 + jn * 8 + 2 * col;
            const float b0 = bias[n], b1 = bias[n + 1];
            float v0 = acc[im][jn][0] + b0, v1 = acc[im][jn][1] + b1;
            float v2 = acc[im][jn][2] + b0, v3 = acc[im][jn][3] + b1;
            if (EPI == EPI_GELU) {
                v0 = 0.5f * v0 * (1.0f + erff(v0 * 0.70710678118654752f));
                v1 = 0.5f * v1 * (1.0f + erff(v1 * 0.70710678118654752f));
                v2 = 0.5f * v2 * (1.0f + erff(v2 * 0.70710678118654752f));
                v3 = 0.5f * v3 * (1.0f + erff(v3 * 0.70710678118654752f));
            } else if (EPI == EPI_SCATTER || EPI == EPI_RES) {
                v0 += res[o0 * N + n]; v1 += res[o0 * N + n + 1];
                v2 += res[o1 * N + n]; v3 += res[o1 * N + n + 1];
            }
            *(float2*)(C + o0 * N + n) = make_float2(v0, v1);
            *(float2*)(C + o1 * N + n) = make_float2(v2, v3);
        }
    }
}

// ---------------- Windowed attention -----------------------------------------
__global__ __launch_bounds__(128)
void attn_kernel(const float* __restrict__ qkv, const float* __restrict__ rel_tab,
                 float* __restrict__ out)
{
    __shared__ float Qs[NTOK][33], Ks[NTOK][33], Vs[NTOK][33];
    __shared__ float S[NTOK * NTOK];

    const int bi = blockIdx.x;
    const int h  = bi & 15;
    const int r  = bi >> 4;
    const int wi = r & 63;
    const int tid = threadIdx.x;

    const float* base = qkv + (size_t)r * NTOK * 1536 + h * 32;
    for (int e = tid; e < NTOK * 32; e += 128) {
        int n = e >> 5, d = e & 31;
        Qs[n][d] = base[n * 1536 + d] * SCALE_;
        Ks[n][d] = base[n * 1536 + 512 + d];
        Vs[n][d] = base[n * 1536 + 1024 + d];
    }
    __syncthreads();

    const int wh = wi >> 3, ww = wi & 7;
    for (int e = tid; e < NTOK * NTOK; e += 128) {
        int i = e / NTOK, j = e % NTOK;
        float s = 0.0f;
        #pragma unroll
        for (int d = 0; d < 32; d++) s = fmaf(Qs[i][d], Ks[j][d], s);
        int ih = i / 7, iw = i % 7, jh = j / 7, jw = j % 7;
        int ridx = (ih - jh + 6) * 13 + (iw - jw + 6);
        s += rel_tab[ridx * NH_ + h];
        int hi = wh * 7 + ih, wgi = ww * 7 + iw;
        int hj = wh * 7 + jh, wgj = ww * 7 + jw;
        int li = ((hi < 49) ? 0 : (hi < 53) ? 1 : 2) * 3 + ((wgi < 49) ? 0 : (wgi < 53) ? 1 : 2);
        int lj = ((hj < 49) ? 0 : (hj < 53) ? 1 : 2) * 3 + ((wgj < 49) ? 0 : (wgj < 53) ? 1 : 2);
        if (li != lj) s -= 100.0f;
        S[e] = s;
    }
    __syncthreads();

    const int warp = tid >> 5, lane = tid & 31;
    for (int i = warp; i < NTOK; i += 4) {
        float mx = -1e30f;
        for (int j = lane; j < NTOK; j += 32) mx = fmaxf(mx, S[i * NTOK + j]);
        #pragma unroll
        for (int o = 16; o; o >>= 1) mx = fmaxf(mx, __shfl_xor_sync(0xffffffffu, mx, o));
        float sum = 0.0f;
        for (int j = lane; j < NTOK; j += 32) {
            float p = expf(S[i * NTOK + j] - mx);
            S[i * NTOK + j] = p;
            sum += p;
        }
        #pragma unroll
        for (int o = 16; o; o >>= 1) sum += __shfl_xor_sync(0xffffffffu, sum, o);
        float inv = 1.0f / sum;
        for (int j = lane; j < NTOK; j += 32) S[i * NTOK + j] *= inv;
    }
    __syncthreads();

    float* obase = out + (size_t)r * NTOK * 512 + h * 32;
    for (int e = tid; e < NTOK * 32; e += 128) {
        int i = e >> 5, d = e & 31;
        float acc = 0.0f;
        #pragma unroll
        for (int j = 0; j < NTOK; j++) acc = fmaf(S[i * NTOK + j], Vs[j][d], acc);
        obase[i * 512 + d] = acc;
    }
}

// ---------------- launcher ----------------------------------------------------
extern "C" void kernel_launch(void* const* d_in, const int* in_sizes, int n_in,
                              void* d_out, int out_size)
{
    const float* x1      = (const float*)d_in[0];
    const float* norm1_g = (const float*)d_in[2];
    const float* norm1_b = (const float*)d_in[3];
    const float* qkv_w   = (const float*)d_in[4];
    const float* qkv_b   = (const float*)d_in[5];
    const float* rel_tab = (const float*)d_in[6];
    const float* proj_w  = (const float*)d_in[7];
    const float* proj_b  = (const float*)d_in[8];
    const float* norm2_g = (const float*)d_in[9];
    const float* norm2_b = (const float*)d_in[10];
    const float* fc1_w   = (const float*)d_in[11];
    const float* fc1_b   = (const float*)d_in[12];
    const float* fc2_w   = (const float*)d_in[13];
    const float* fc2_b   = (const float*)d_in[14];

    float *a1w, *qkvb, *attnb, *xb, *ln2b, *h1b;
    cudaGetSymbolAddress((void**)&a1w,   g_a1w);
    cudaGetSymbolAddress((void**)&qkvb,  g_qkv);
    cudaGetSymbolAddress((void**)&attnb, g_attn);
    cudaGetSymbolAddress((void**)&xb,    g_x);
    cudaGetSymbolAddress((void**)&ln2b,  g_ln2);
    cudaGetSymbolAddress((void**)&h1b,   g_h1);

    cudaFuncSetAttribute(gemm_tc<EPI_NONE>,    cudaFuncAttributeMaxDynamicSharedMemorySize, SMEM_BYTES);
    cudaFuncSetAttribute(gemm_tc<EPI_GELU>,    cudaFuncAttributeMaxDynamicSharedMemorySize, SMEM_BYTES);
    cudaFuncSetAttribute(gemm_tc<EPI_SCATTER>, cudaFuncAttributeMaxDynamicSharedMemorySize, SMEM_BYTES);
    cudaFuncSetAttribute(gemm_tc<EPI_RES>,     cudaFuncAttributeMaxDynamicSharedMemorySize, SMEM_BYTES);

    // 1) LN1 + roll(-3,-3) + window partition
    ln_kernel<1><<<MROWS, 128>>>(x1, norm1_g, norm1_b, a1w);

    // 2) QKV projection
    {
        dim3 grid(1536 / 128, MROWS / 128);
        gemm_tc<EPI_NONE><<<grid, 256, SMEM_BYTES>>>(a1w, qkv_w, qkv_b, qkvb, nullptr,
                                                     MROWS, 1536, 512);
    }

    // 3) windowed attention
    attn_kernel<<<B_ * NWIN * NH_, 128>>>(qkvb, rel_tab, attnb);

    // 4) proj + reverse + roll + residual
    {
        dim3 grid(512 / 128, MROWS / 128);
        gemm_tc<EPI_SCATTER><<<grid, 256, SMEM_BYTES>>>(attnb, proj_w, proj_b, xb, x1,
                                                        MROWS, 512, 512);
    }

    // 5) LN2
    ln_kernel<0><<<MROWS, 128>>>(xb, norm2_g, norm2_b, ln2b);

    // 6) fc1 + exact GELU
    {
        dim3 grid(2048 / 128, MROWS / 128);
        gemm_tc<EPI_GELU><<<grid, 256, SMEM_BYTES>>>(ln2b, fc1_w, fc1_b, h1b, nullptr,
                                                     MROWS, 2048, 512);
    }

    // 7) fc2 + residual -> out
    {
        dim3 grid(512 / 128, MROWS / 128);
        gemm_tc<EPI_RES><<<grid, 256, SMEM_BYTES>>>(h1b, fc2_w, fc2_b, (float*)d_out, xb,
                                                    MROWS, 512, 2048);
    }
}

// round 5
// speedup vs baseline: 3.7400x; 1.0398x over previous
#include <cuda_runtime.h>
#include <math.h>
#include <stdint.h>

// Problem constants
#define B_    16
#define HH    56
#define WW_   56
#define C_    512
#define NH_   16
#define WS_   7
#define SS_   3
#define NTOK  49
#define NWIN  64
#define HD_   32
#define MLPH  2048
#define MROWS 50176
#define SCALE_ 0.17677669529663687f

// ---------------- scratch ----------------------------------------------------
__device__ float g_a1w [(size_t)MROWS * 512];
__device__ float g_qkv [(size_t)MROWS * 1536];
__device__ float g_attn[(size_t)MROWS * 512];
__device__ float g_x   [(size_t)MROWS * 512];
__device__ float g_ln2 [(size_t)MROWS * 512];
__device__ float g_h1  [(size_t)MROWS * 2048];
// tf32-pre-rounded weights
__device__ float g_wq [1536 * 512];
__device__ float g_wp [512 * 512];
__device__ float g_w1 [2048 * 512];
__device__ float g_w2 [512 * 2048];

__device__ __forceinline__ float tf32r(float x) {
    uint32_t r; asm("cvt.rna.tf32.f32 %0, %1;" : "=r"(r) : "f"(x));
    return __uint_as_float(r);
}

// round a weight matrix to tf32 precision (done each launch; deterministic)
__global__ __launch_bounds__(256)
void round_kernel(const float* __restrict__ src, float* __restrict__ dst, int n)
{
    int i = blockIdx.x * 1024 + threadIdx.x * 4;
    if (i < n) {
        float4 v = *(const float4*)(src + i);
        v.x = tf32r(v.x); v.y = tf32r(v.y); v.z = tf32r(v.z); v.w = tf32r(v.w);
        *(float4*)(dst + i) = v;
    }
}

// ---------------- LayerNorm (outputs tf32-rounded; only feed TC GEMMs) --------
template <int MODE>
__global__ __launch_bounds__(128)
void ln_kernel(const float* __restrict__ src, const float* __restrict__ g,
               const float* __restrict__ b, float* __restrict__ dst)
{
    const int m = blockIdx.x;
    const float* row;
    if (MODE == 1) {
        int r  = m / NTOK, nt = m % NTOK;
        int bb = r >> 6,   wi = r & 63;
        int wh = wi >> 3,  ww = wi & 7;
        int ih = nt / 7,   iw = nt % 7;
        int hs = wh * 7 + ih + SS_; if (hs >= HH)  hs -= HH;
        int ws = ww * 7 + iw + SS_; if (ws >= WW_) ws -= WW_;
        row = src + ((size_t)bb * 3136 + hs * 56 + ws) * 512;
    } else {
        row = src + (size_t)m * 512;
    }
    const int t = threadIdx.x;
    float4 v = *(const float4*)(row + t * 4);
    float s = v.x + v.y + v.z + v.w;
    float q = v.x * v.x + v.y * v.y + v.z * v.z + v.w * v.w;
    #pragma unroll
    for (int o = 16; o; o >>= 1) {
        s += __shfl_xor_sync(0xffffffffu, s, o);
        q += __shfl_xor_sync(0xffffffffu, q, o);
    }
    __shared__ float red[8];
    int warp = t >> 5, lane = t & 31;
    if (lane == 0) { red[warp] = s; red[warp + 4] = q; }
    __syncthreads();
    s = red[0] + red[1] + red[2] + red[3];
    q = red[4] + red[5] + red[6] + red[7];
    float mean = s * (1.0f / 512.0f);
    float var  = q * (1.0f / 512.0f) - mean * mean;
    float rstd = rsqrtf(var + 1e-5f);
    float4 gv = *(const float4*)(g + t * 4);
    float4 bv = *(const float4*)(b + t * 4);
    float4 o4;
    o4.x = tf32r((v.x - mean) * rstd * gv.x + bv.x);
    o4.y = tf32r((v.y - mean) * rstd * gv.y + bv.y);
    o4.z = tf32r((v.z - mean) * rstd * gv.z + bv.z);
    o4.w = tf32r((v.w - mean) * rstd * gv.w + bv.w);
    *(float4*)(dst + (size_t)m * 512 + t * 4) = o4;
}

// ---------------- TF32 tensor-core GEMM --------------------------------------
enum { EPI_NONE = 0, EPI_GELU = 1, EPI_SCATTER = 2, EPI_RES = 3 };

#define LDT 36
#define ASZ (128 * LDT)
#define SMEM_BYTES (4 * ASZ * 4)

__device__ __forceinline__ void mma8(float* c, const uint32_t* a, const uint32_t* b) {
    asm volatile(
        "mma.sync.aligned.m16n8k8.row.col.f32.tf32.tf32.f32 "
        "{%0,%1,%2,%3},{%4,%5,%6,%7},{%8,%9},{%0,%1,%2,%3};\n"
        : "+f"(c[0]), "+f"(c[1]), "+f"(c[2]), "+f"(c[3])
        : "r"(a[0]), "r"(a[1]), "r"(a[2]), "r"(a[3]), "r"(b[0]), "r"(b[1]));
}
__device__ __forceinline__ void cp16(uint32_t dst, const void* src) {
    asm volatile("cp.async.cg.shared.global [%0], [%1], 16;\n" :: "r"(dst), "l"(src));
}
__device__ __forceinline__ void cp_commit() { asm volatile("cp.async.commit_group;\n"); }
__device__ __forceinline__ void cp_wait0()  { asm volatile("cp.async.wait_group 0;\n"); }

__device__ __forceinline__ size_t scatter_row(int m) {
    int r  = m / NTOK, nt = m % NTOK;
    int bb = r >> 6,   wi = r & 63;
    int wh = wi >> 3,  ww = wi & 7;
    int ih = nt / 7,   iw = nt % 7;
    int h = wh * 7 + ih + SS_; if (h >= HH)  h -= HH;
    int w = ww * 7 + iw + SS_; if (w >= WW_) w -= WW_;
    return (size_t)bb * 3136 + h * 56 + w;
}

template <int EPI>
__global__ __launch_bounds__(256, 2)
void gemm_tc(const float* __restrict__ A, const float* __restrict__ Bw,
             const float* __restrict__ bias, float* __restrict__ C,
             const float* __restrict__ res, int M, int N, int K)
{
    extern __shared__ float sm[];
    const int tid  = threadIdx.x;
    const int lane = tid & 31, warp = tid >> 5;
    const int wm = warp & 1, wn = warp >> 1;
    const int row = lane >> 2, col = lane & 3;
    const int m0 = blockIdx.y * 128, n0 = blockIdx.x * 128;

    float acc[4][4][4];
    #pragma unroll
    for (int i = 0; i < 4; i++)
        #pragma unroll
        for (int j = 0; j < 4; j++)
            #pragma unroll
            for (int t = 0; t < 4; t++) acc[i][j][t] = 0.0f;

    const int ldRow = tid >> 1;
    const int ldCol = (tid & 1) * 16;
    const float* aSrc = A  + (size_t)(m0 + ldRow) * K + ldCol;
    const float* bSrc = Bw + (size_t)(n0 + ldRow) * K + ldCol;
    const uint32_t smBase = (uint32_t)__cvta_generic_to_shared(sm);
    const uint32_t aDst = smBase + (uint32_t)(ldRow * LDT + ldCol) * 4;
    const uint32_t bDst = smBase + (uint32_t)(2 * ASZ + ldRow * LDT + ldCol) * 4;

    const int niter = K >> 5;

    #pragma unroll
    for (int p = 0; p < 4; p++) cp16(aDst + p * 16, aSrc + p * 4);
    #pragma unroll
    for (int p = 0; p < 4; p++) cp16(bDst + p * 16, bSrc + p * 4);
    cp_commit();

    int buf = 0;
    for (int it = 0; it < niter; it++) {
        cp_wait0();
        __syncthreads();

        if (it + 1 < niter) {
            const int nb = buf ^ 1;
            const float* as = aSrc + (it + 1) * 32;
            const float* bs = bSrc + (it + 1) * 32;
            const uint32_t ao = aDst + (uint32_t)(nb * ASZ) * 4;
            const uint32_t bo = bDst + (uint32_t)(nb * ASZ) * 4;
            #pragma unroll
            for (int p = 0; p < 4; p++) cp16(ao + p * 16, as + p * 4);
            #pragma unroll
            for (int p = 0; p < 4; p++) cp16(bo + p * 16, bs + p * 4);
            cp_commit();
        }

        const float* Ab = sm + buf * ASZ;
        const float* Bb = sm + 2 * ASZ + buf * ASZ;

        #pragma unroll
        for (int kk = 0; kk < 32; kk += 8) {
            uint32_t af[4][4], bf[4][2];
            #pragma unroll
            for (int im = 0; im < 4; im++) {
                const int mb = wm * 64 + im * 16 + row;
                af[im][0] = __float_as_uint(Ab[(mb)     * LDT + kk + col]);
                af[im][1] = __float_as_uint(Ab[(mb + 8) * LDT + kk + col]);
                af[im][2] = __float_as_uint(Ab[(mb)     * LDT + kk + col + 4]);
                af[im][3] = __float_as_uint(Ab[(mb + 8) * LDT + kk + col + 4]);
            }
            #pragma unroll
            for (int jn = 0; jn < 4; jn++) {
                const int nb2 = wn * 32 + jn * 8 + row;
                bf[jn][0] = __float_as_uint(Bb[nb2 * LDT + kk + col]);
                bf[jn][1] = __float_as_uint(Bb[nb2 * LDT + kk + col + 4]);
            }
            #pragma unroll
            for (int im = 0; im < 4; im++)
                #pragma unroll
                for (int jn = 0; jn < 4; jn++)
                    mma8(acc[im][jn], af[im], bf[jn]);
        }
        buf ^= 1;
    }

    #pragma unroll
    for (int im = 0; im < 4; im++) {
        const int r0 = m0 + wm * 64 + im * 16 + row;
        const int r1 = r0 + 8;
        size_t o0, o1;
        if (EPI == EPI_SCATTER) { o0 = scatter_row(r0); o1 = scatter_row(r1); }
        else                    { o0 = (size_t)r0;      o1 = (size_t)r1; }
        #pragma unroll
        for (int jn = 0; jn < 4; jn++) {
            const int n = n0 + wn * 32 + jn * 8 + 2 * col;
            const float b0 = bias[n], b1 = bias[n + 1];
            float v0 = acc[im][jn][0] + b0, v1 = acc[im][jn][1] + b1;
            float v2 = acc[im][jn][2] + b0, v3 = acc[im][jn][3] + b1;
            if (EPI == EPI_GELU) {
                v0 = tf32r(0.5f * v0 * (1.0f + erff(v0 * 0.70710678118654752f)));
                v1 = tf32r(0.5f * v1 * (1.0f + erff(v1 * 0.70710678118654752f)));
                v2 = tf32r(0.5f * v2 * (1.0f + erff(v2 * 0.70710678118654752f)));
                v3 = tf32r(0.5f * v3 * (1.0f + erff(v3 * 0.70710678118654752f)));
            } else if (EPI == EPI_SCATTER || EPI == EPI_RES) {
                v0 += res[o0 * N + n]; v1 += res[o0 * N + n + 1];
                v2 += res[o1 * N + n]; v3 += res[o1 * N + n + 1];
            }
            *(float2*)(C + o0 * N + n) = make_float2(v0, v1);
            *(float2*)(C + o1 * N + n) = make_float2(v2, v3);
        }
    }
}

// ---------------- Windowed attention (outputs tf32-rounded for proj GEMM) -----
__global__ __launch_bounds__(128)
void attn_kernel(const float* __restrict__ qkv, const float* __restrict__ rel_tab,
                 float* __restrict__ out)
{
    __shared__ float Qs[NTOK][33], Ks[NTOK][33], Vs[NTOK][33];
    __shared__ float S[NTOK * NTOK];

    const int bi = blockIdx.x;
    const int h  = bi & 15;
    const int r  = bi >> 4;
    const int wi = r & 63;
    const int tid = threadIdx.x;

    const float* base = qkv + (size_t)r * NTOK * 1536 + h * 32;
    for (int e = tid; e < NTOK * 32; e += 128) {
        int n = e >> 5, d = e & 31;
        Qs[n][d] = base[n * 1536 + d] * SCALE_;
        Ks[n][d] = base[n * 1536 + 512 + d];
        Vs[n][d] = base[n * 1536 + 1024 + d];
    }
    __syncthreads();

    const int wh = wi >> 3, ww = wi & 7;
    for (int e = tid; e < NTOK * NTOK; e += 128) {
        int i = e / NTOK, j = e % NTOK;
        float s = 0.0f;
        #pragma unroll
        for (int d = 0; d < 32; d++) s = fmaf(Qs[i][d], Ks[j][d], s);
        int ih = i / 7, iw = i % 7, jh = j / 7, jw = j % 7;
        int ridx = (ih - jh + 6) * 13 + (iw - jw + 6);
        s += rel_tab[ridx * NH_ + h];
        int hi = wh * 7 + ih, wgi = ww * 7 + iw;
        int hj = wh * 7 + jh, wgj = ww * 7 + jw;
        int li = ((hi < 49) ? 0 : (hi < 53) ? 1 : 2) * 3 + ((wgi < 49) ? 0 : (wgi < 53) ? 1 : 2);
        int lj = ((hj < 49) ? 0 : (hj < 53) ? 1 : 2) * 3 + ((wgj < 49) ? 0 : (wgj < 53) ? 1 : 2);
        if (li != lj) s -= 100.0f;
        S[e] = s;
    }
    __syncthreads();

    const int warp = tid >> 5, lane = tid & 31;
    for (int i = warp; i < NTOK; i += 4) {
        float mx = -1e30f;
        for (int j = lane; j < NTOK; j += 32) mx = fmaxf(mx, S[i * NTOK + j]);
        #pragma unroll
        for (int o = 16; o; o >>= 1) mx = fmaxf(mx, __shfl_xor_sync(0xffffffffu, mx, o));
        float sum = 0.0f;
        for (int j = lane; j < NTOK; j += 32) {
            float p = expf(S[i * NTOK + j] - mx);
            S[i * NTOK + j] = p;
            sum += p;
        }
        #pragma unroll
        for (int o = 16; o; o >>= 1) sum += __shfl_xor_sync(0xffffffffu, sum, o);
        float inv = 1.0f / sum;
        for (int j = lane; j < NTOK; j += 32) S[i * NTOK + j] *= inv;
    }
    __syncthreads();

    float* obase = out + (size_t)r * NTOK * 512 + h * 32;
    for (int e = tid; e < NTOK * 32; e += 128) {
        int i = e >> 5, d = e & 31;
        float acc = 0.0f;
        #pragma unroll
        for (int j = 0; j < NTOK; j++) acc = fmaf(S[i * NTOK + j], Vs[j][d], acc);
        obase[i * 512 + d] = tf32r(acc);
    }
}

// ---------------- launcher ----------------------------------------------------
extern "C" void kernel_launch(void* const* d_in, const int* in_sizes, int n_in,
                              void* d_out, int out_size)
{
    const float* x1      = (const float*)d_in[0];
    const float* norm1_g = (const float*)d_in[2];
    const float* norm1_b = (const float*)d_in[3];
    const float* qkv_w   = (const float*)d_in[4];
    const float* qkv_b   = (const float*)d_in[5];
    const float* rel_tab = (const float*)d_in[6];
    const float* proj_w  = (const float*)d_in[7];
    const float* proj_b  = (const float*)d_in[8];
    const float* norm2_g = (const float*)d_in[9];
    const float* norm2_b = (const float*)d_in[10];
    const float* fc1_w   = (const float*)d_in[11];
    const float* fc1_b   = (const float*)d_in[12];
    const float* fc2_w   = (const float*)d_in[13];
    const float* fc2_b   = (const float*)d_in[14];

    float *a1w, *qkvb, *attnb, *xb, *ln2b, *h1b, *wq, *wp, *w1, *w2;
    cudaGetSymbolAddress((void**)&a1w,   g_a1w);
    cudaGetSymbolAddress((void**)&qkvb,  g_qkv);
    cudaGetSymbolAddress((void**)&attnb, g_attn);
    cudaGetSymbolAddress((void**)&xb,    g_x);
    cudaGetSymbolAddress((void**)&ln2b,  g_ln2);
    cudaGetSymbolAddress((void**)&h1b,   g_h1);
    cudaGetSymbolAddress((void**)&wq,    g_wq);
    cudaGetSymbolAddress((void**)&wp,    g_wp);
    cudaGetSymbolAddress((void**)&w1,    g_w1);
    cudaGetSymbolAddress((void**)&w2,    g_w2);

    cudaFuncSetAttribute(gemm_tc<EPI_NONE>,    cudaFuncAttributeMaxDynamicSharedMemorySize, SMEM_BYTES);
    cudaFuncSetAttribute(gemm_tc<EPI_GELU>,    cudaFuncAttributeMaxDynamicSharedMemorySize, SMEM_BYTES);
    cudaFuncSetAttribute(gemm_tc<EPI_SCATTER>, cudaFuncAttributeMaxDynamicSharedMemorySize, SMEM_BYTES);
    cudaFuncSetAttribute(gemm_tc<EPI_RES>,     cudaFuncAttributeMaxDynamicSharedMemorySize, SMEM_BYTES);

    // 0) pre-round weights to tf32
    round_kernel<<<(1536 * 512) / 1024, 256>>>(qkv_w, wq, 1536 * 512);
    round_kernel<<<(512  * 512) / 1024, 256>>>(proj_w, wp, 512 * 512);
    round_kernel<<<(2048 * 512) / 1024, 256>>>(fc1_w, w1, 2048 * 512);
    round_kernel<<<(512 * 2048) / 1024, 256>>>(fc2_w, w2, 512 * 2048);

    // 1) LN1 + roll + partition (tf32-rounded out)
    ln_kernel<1><<<MROWS, 128>>>(x1, norm1_g, norm1_b, a1w);

    // 2) QKV projection
    {
        dim3 grid(1536 / 128, MROWS / 128);
        gemm_tc<EPI_NONE><<<grid, 256, SMEM_BYTES>>>(a1w, wq, qkv_b, qkvb, nullptr,
                                                     MROWS, 1536, 512);
    }

    // 3) windowed attention
    attn_kernel<<<B_ * NWIN * NH_, 128>>>(qkvb, rel_tab, attnb);

    // 4) proj + reverse + roll + residual
    {
        dim3 grid(512 / 128, MROWS / 128);
        gemm_tc<EPI_SCATTER><<<grid, 256, SMEM_BYTES>>>(attnb, wp, proj_b, xb, x1,
                                                        MROWS, 512, 512);
    }

    // 5) LN2 (tf32-rounded out)
    ln_kernel<0><<<MROWS, 128>>>(xb, norm2_g, norm2_b, ln2b);

    // 6) fc1 + exact GELU (tf32-rounded out)
    {
        dim3 grid(2048 / 128, MROWS / 128);
        gemm_tc<EPI_GELU><<<grid, 256, SMEM_BYTES>>>(ln2b, w1, fc1_b, h1b, nullptr,
                                                     MROWS, 2048, 512);
    }

    // 7) fc2 + residual -> out
    {
        dim3 grid(512 / 128, MROWS / 128);
        gemm_tc<EPI_RES><<<grid, 256, SMEM_BYTES>>>(h1b, w2, fc2_b, (float*)d_out, xb,
                                                    MROWS, 512, 2048);
    }
}

// round 8
// speedup vs baseline: 6.2515x; 1.6715x over previous
#include <cuda_runtime.h>
#include <cuda_fp16.h>
#include <math.h>
#include <stdint.h>

// Problem constants
#define B_    16
#define HH    56
#define WW_   56
#define C_    512
#define NH_   16
#define WS_   7
#define SS_   3
#define NTOK  49
#define NWIN  64
#define HD_   32
#define MLPH  2048
#define MROWS 50176
#define SCALE_ 0.17677669529663687f

// ---------------- scratch ----------------------------------------------------
__device__ __half g_a1w [(size_t)MROWS * 512];    // LN1 out (fp16)
__device__ __half g_qkv [(size_t)MROWS * 1536];   // qkv (fp16)
__device__ __half g_attn[(size_t)MROWS * 512];    // attention out (fp16)
__device__ float  g_x   [(size_t)MROWS * 512];    // residual stream (fp32)
__device__ __half g_ln2 [(size_t)MROWS * 512];    // LN2 out (fp16)
__device__ __half g_h1  [(size_t)MROWS * 2048];   // fc1+gelu out (fp16)
// fp16 weights
__device__ __half g_wq [1536 * 512];
__device__ __half g_wp [512 * 512];
__device__ __half g_w1 [2048 * 512];
__device__ __half g_w2 [512 * 2048];

// fp32 -> fp16 weight conversion
__global__ __launch_bounds__(256)
void round_kernel(const float* __restrict__ src, __half* __restrict__ dst, int n)
{
    int i = blockIdx.x * 1024 + threadIdx.x * 4;
    if (i < n) {
        float4 v = *(const float4*)(src + i);
        __half2 h0 = __floats2half2_rn(v.x, v.y);
        __half2 h1 = __floats2half2_rn(v.z, v.w);
        *(__half2*)(dst + i)     = h0;
        *(__half2*)(dst + i + 2) = h1;
    }
}

// ---------------- LayerNorm (fp32 in -> fp16 out) -----------------------------
template <int MODE>
__global__ __launch_bounds__(128)
void ln_kernel(const float* __restrict__ src, const float* __restrict__ g,
               const float* __restrict__ b, __half* __restrict__ dst)
{
    const int m = blockIdx.x;
    const float* row;
    if (MODE == 1) {
        int r  = m / NTOK, nt = m % NTOK;
        int bb = r >> 6,   wi = r & 63;
        int wh = wi >> 3,  ww = wi & 7;
        int ih = nt / 7,   iw = nt % 7;
        int hs = wh * 7 + ih + SS_; if (hs >= HH)  hs -= HH;
        int ws = ww * 7 + iw + SS_; if (ws >= WW_) ws -= WW_;
        row = src + ((size_t)bb * 3136 + hs * 56 + ws) * 512;
    } else {
        row = src + (size_t)m * 512;
    }
    const int t = threadIdx.x;
    float4 v = *(const float4*)(row + t * 4);
    float s = v.x + v.y + v.z + v.w;
    float q = v.x * v.x + v.y * v.y + v.z * v.z + v.w * v.w;
    #pragma unroll
    for (int o = 16; o; o >>= 1) {
        s += __shfl_xor_sync(0xffffffffu, s, o);
        q += __shfl_xor_sync(0xffffffffu, q, o);
    }
    __shared__ float red[8];
    int warp = t >> 5, lane = t & 31;
    if (lane == 0) { red[warp] = s; red[warp + 4] = q; }
    __syncthreads();
    s = red[0] + red[1] + red[2] + red[3];
    q = red[4] + red[5] + red[6] + red[7];
    float mean = s * (1.0f / 512.0f);
    float var  = q * (1.0f / 512.0f) - mean * mean;
    float rstd = rsqrtf(var + 1e-5f);
    float4 gv = *(const float4*)(g + t * 4);
    float4 bv = *(const float4*)(b + t * 4);
    __half2 h0 = __floats2half2_rn((v.x - mean) * rstd * gv.x + bv.x,
                                   (v.y - mean) * rstd * gv.y + bv.y);
    __half2 h1 = __floats2half2_rn((v.z - mean) * rstd * gv.z + bv.z,
                                   (v.w - mean) * rstd * gv.w + bv.w);
    *(__half2*)(dst + (size_t)m * 512 + t * 4)     = h0;
    *(__half2*)(dst + (size_t)m * 512 + t * 4 + 2) = h1;
}

// ---------------- fp16 tensor-core GEMM (m16n8k16, fp32 accum) ----------------
enum { EPI_NONE = 0, EPI_GELU = 1, EPI_SCATTER = 2, EPI_RES = 3 };

#define LDTH 40                 // pitch in halves (80B): conflict-free frags
#define ASZH (128 * LDTH)       // halves per matrix per buffer
#define SMEM_BYTES (4 * ASZH * 2)

__device__ __forceinline__ void mma16(float* c, const uint32_t* a, const uint32_t* b) {
    asm volatile(
        "mma.sync.aligned.m16n8k16.row.col.f32.f16.f16.f32 "
        "{%0,%1,%2,%3},{%4,%5,%6,%7},{%8,%9},{%0,%1,%2,%3};\n"
        : "+f"(c[0]), "+f"(c[1]), "+f"(c[2]), "+f"(c[3])
        : "r"(a[0]), "r"(a[1]), "r"(a[2]), "r"(a[3]), "r"(b[0]), "r"(b[1]));
}
__device__ __forceinline__ void cp16(uint32_t dst, const void* src) {
    asm volatile("cp.async.cg.shared.global [%0], [%1], 16;\n" :: "r"(dst), "l"(src));
}
__device__ __forceinline__ void cp_commit() { asm volatile("cp.async.commit_group;\n"); }
__device__ __forceinline__ void cp_wait0()  { asm volatile("cp.async.wait_group 0;\n"); }

__device__ __forceinline__ size_t scatter_row(int m) {
    int r  = m / NTOK, nt = m % NTOK;
    int bb = r >> 6,   wi = r & 63;
    int wh = wi >> 3,  ww = wi & 7;
    int ih = nt / 7,   iw = nt % 7;
    int h = wh * 7 + ih + SS_; if (h >= HH)  h -= HH;
    int w = ww * 7 + iw + SS_; if (w >= WW_) w -= WW_;
    return (size_t)bb * 3136 + h * 56 + w;
}

// A [M,K] fp16 row-major, B [N,K] fp16 row-major; C = A @ B^T + bias.
template <int EPI>
__global__ __launch_bounds__(256, 2)
void gemm_tc(const __half* __restrict__ A, const __half* __restrict__ Bw,
             const float* __restrict__ bias, void* __restrict__ Cv,
             const float* __restrict__ res, int M, int N, int K)
{
    extern __shared__ __half sm[];
    const int tid  = threadIdx.x;
    const int lane = tid & 31, warp = tid >> 5;
    const int wm = warp & 1, wn = warp >> 1;          // 2 x 4 warp grid, warp tile 64x32
    const int row = lane >> 2, col = lane & 3;
    const int m0 = blockIdx.y * 128, n0 = blockIdx.x * 128;

    float acc[4][4][4];
    #pragma unroll
    for (int i = 0; i < 4; i++)
        #pragma unroll
        for (int j = 0; j < 4; j++)
            #pragma unroll
            for (int t = 0; t < 4; t++) acc[i][j][t] = 0.0f;

    // loader: each thread owns one row, 16 halves (2 x 16B chunks)
    const int ldRow = tid >> 1;
    const int ldCol = (tid & 1) * 16;
    const __half* aSrc = A  + (size_t)(m0 + ldRow) * K + ldCol;
    const __half* bSrc = Bw + (size_t)(n0 + ldRow) * K + ldCol;
    const uint32_t smBase = (uint32_t)__cvta_generic_to_shared(sm);
    const uint32_t aDst = smBase + (uint32_t)(ldRow * LDTH + ldCol) * 2;
    const uint32_t bDst = smBase + (uint32_t)(2 * ASZH + ldRow * LDTH + ldCol) * 2;

    const int niter = K >> 5;   // BK = 32 halves

    #pragma unroll
    for (int p = 0; p < 2; p++) cp16(aDst + p * 16, aSrc + p * 8);
    #pragma unroll
    for (int p = 0; p < 2; p++) cp16(bDst + p * 16, bSrc + p * 8);
    cp_commit();

    int buf = 0;
    for (int it = 0; it < niter; it++) {
        cp_wait0();
        __syncthreads();

        if (it + 1 < niter) {
            const int nb = buf ^ 1;
            const __half* as = aSrc + (it + 1) * 32;
            const __half* bs = bSrc + (it + 1) * 32;
            const uint32_t ao = aDst + (uint32_t)(nb * ASZH) * 2;
            const uint32_t bo = bDst + (uint32_t)(nb * ASZH) * 2;
            #pragma unroll
            for (int p = 0; p < 2; p++) cp16(ao + p * 16, as + p * 8);
            #pragma unroll
            for (int p = 0; p < 2; p++) cp16(bo + p * 16, bs + p * 8);
            cp_commit();
        }

        const __half* Ab = sm + buf * ASZH;
        const __half* Bb = sm + 2 * ASZH + buf * ASZH;

        #pragma unroll
        for (int kk = 0; kk < 32; kk += 16) {
            uint32_t af[4][4], bf[4][2];
            #pragma unroll
            for (int im = 0; im < 4; im++) {
                const int mb = wm * 64 + im * 16 + row;
                const __half* p0 = Ab + (mb)     * LDTH + kk + 2 * col;
                const __half* p1 = Ab + (mb + 8) * LDTH + kk + 2 * col;
                af[im][0] = *(const uint32_t*)(p0);
                af[im][1] = *(const uint32_t*)(p1);
                af[im][2] = *(const uint32_t*)(p0 + 8);
                af[im][3] = *(const uint32_t*)(p1 + 8);
            }
            #pragma unroll
            for (int jn = 0; jn < 4; jn++) {
                const int nb2 = wn * 32 + jn * 8 + row;
                const __half* p = Bb + nb2 * LDTH + kk + 2 * col;
                bf[jn][0] = *(const uint32_t*)(p);
                bf[jn][1] = *(const uint32_t*)(p + 8);
            }
            #pragma unroll
            for (int im = 0; im < 4; im++)
                #pragma unroll
                for (int jn = 0; jn < 4; jn++)
                    mma16(acc[im][jn], af[im], bf[jn]);
        }
        buf ^= 1;
    }

    // epilogue
    #pragma unroll
    for (int im = 0; im < 4; im++) {
        const int r0 = m0 + wm * 64 + im * 16 + row;
        const int r1 = r0 + 8;
        size_t o0, o1;
        if (EPI == EPI_SCATTER) { o0 = scatter_row(r0); o1 = scatter_row(r1); }
        else                    { o0 = (size_t)r0;      o1 = (size_t)r1; }
        #pragma unroll
        for (int jn = 0; jn < 4; jn++) {
            const int n = n0 + wn * 32 + jn * 8 + 2 * col;
            const float b0 = bias[n], b1 = bias[n + 1];
            float v0 = acc[im][jn][0] + b0, v1 = acc[im][jn][1] + b1;
            float v2 = acc[im][jn][2] + b0, v3 = acc[im][jn][3] + b1;
            if (EPI == EPI_GELU) {
                v0 = 0.5f * v0 * (1.0f + erff(v0 * 0.70710678118654752f));
                v1 = 0.5f * v1 * (1.0f + erff(v1 * 0.70710678118654752f));
                v2 = 0.5f * v2 * (1.0f + erff(v2 * 0.70710678118654752f));
                v3 = 0.5f * v3 * (1.0f + erff(v3 * 0.70710678118654752f));
            }
            if (EPI == EPI_NONE || EPI == EPI_GELU) {
                __half* C = (__half*)Cv;
                *(__half2*)(C + o0 * N + n) = __floats2half2_rn(v0, v1);
                *(__half2*)(C + o1 * N + n) = __floats2half2_rn(v2, v3);
            } else {
                float* C = (float*)Cv;
                v0 += res[o0 * N + n]; v1 += res[o0 * N + n + 1];
                v2 += res[o1 * N + n]; v3 += res[o1 * N + n + 1];
                *(float2*)(C + o0 * N + n) = make_float2(v0, v1);
                *(float2*)(C + o1 * N + n) = make_float2(v2, v3);
            }
        }
    }
}

// ---------------- Windowed attention (fp16 in/out, fp32 math) -----------------
__global__ __launch_bounds__(128)
void attn_kernel(const __half* __restrict__ qkv, const float* __restrict__ rel_tab,
                 __half* __restrict__ out)
{
    __shared__ float Qs[NTOK][33], Ks[NTOK][33], Vs[NTOK][33];
    __shared__ float S[NTOK * NTOK];

    const int bi = blockIdx.x;
    const int h  = bi & 15;
    const int r  = bi >> 4;
    const int wi = r & 63;
    const int tid = threadIdx.x;

    const __half* base = qkv + (size_t)r * NTOK * 1536 + h * 32;
    for (int e = tid; e < NTOK * 32; e += 128) {
        int n = e >> 5, d = e & 31;
        Qs[n][d] = __half2float(base[n * 1536 + d]) * SCALE_;
        Ks[n][d] = __half2float(base[n * 1536 + 512 + d]);
        Vs[n][d] = __half2float(base[n * 1536 + 1024 + d]);
    }
    __syncthreads();

    const int wh = wi >> 3, ww = wi & 7;
    for (int e = tid; e < NTOK * NTOK; e += 128) {
        int i = e / NTOK, j = e % NTOK;
        float s = 0.0f;
        #pragma unroll
        for (int d = 0; d < 32; d++) s = fmaf(Qs[i][d], Ks[j][d], s);
        int ih = i / 7, iw = i % 7, jh = j / 7, jw = j % 7;
        int ridx = (ih - jh + 6) * 13 + (iw - jw + 6);
        s += rel_tab[ridx * NH_ + h];
        int hi = wh * 7 + ih, wgi = ww * 7 + iw;
        int hj = wh * 7 + jh, wgj = ww * 7 + jw;
        int li = ((hi < 49) ? 0 : (hi < 53) ? 1 : 2) * 3 + ((wgi < 49) ? 0 : (wgi < 53) ? 1 : 2);
        int lj = ((hj < 49) ? 0 : (hj < 53) ? 1 : 2) * 3 + ((wgj < 49) ? 0 : (wgj < 53) ? 1 : 2);
        if (li != lj) s -= 100.0f;
        S[e] = s;
    }
    __syncthreads();

    const int warp = tid >> 5, lane = tid & 31;
    for (int i = warp; i < NTOK; i += 4) {
        float mx = -1e30f;
        for (int j = lane; j < NTOK; j += 32) mx = fmaxf(mx, S[i * NTOK + j]);
        #pragma unroll
        for (int o = 16; o; o >>= 1) mx = fmaxf(mx, __shfl_xor_sync(0xffffffffu, mx, o));
        float sum = 0.0f;
        for (int j = lane; j < NTOK; j += 32) {
            float p = expf(S[i * NTOK + j] - mx);
            S[i * NTOK + j] = p;
            sum += p;
        }
        #pragma unroll
        for (int o = 16; o; o >>= 1) sum += __shfl_xor_sync(0xffffffffu, sum, o);
        float inv = 1.0f / sum;
        for (int j = lane; j < NTOK; j += 32) S[i * NTOK + j] *= inv;
    }
    __syncthreads();

    __half* obase = out + (size_t)r * NTOK * 512 + h * 32;
    for (int e = tid; e < NTOK * 32; e += 128) {
        int i = e >> 5, d = e & 31;
        float acc = 0.0f;
        #pragma unroll
        for (int j = 0; j < NTOK; j++) acc = fmaf(S[i * NTOK + j], Vs[j][d], acc);
        obase[i * 512 + d] = __float2half_rn(acc);
    }
}

// ---------------- launcher ----------------------------------------------------
extern "C" void kernel_launch(void* const* d_in, const int* in_sizes, int n_in,
                              void* d_out, int out_size)
{
    const float* x1      = (const float*)d_in[0];
    const float* norm1_g = (const float*)d_in[2];
    const float* norm1_b = (const float*)d_in[3];
    const float* qkv_w   = (const float*)d_in[4];
    const float* qkv_b   = (const float*)d_in[5];
    const float* rel_tab = (const float*)d_in[6];
    const float* proj_w  = (const float*)d_in[7];
    const float* proj_b  = (const float*)d_in[8];
    const float* norm2_g = (const float*)d_in[9];
    const float* norm2_b = (const float*)d_in[10];
    const float* fc1_w   = (const float*)d_in[11];
    const float* fc1_b   = (const float*)d_in[12];
    const float* fc2_w   = (const float*)d_in[13];
    const float* fc2_b   = (const float*)d_in[14];

    __half *a1w, *qkvb, *attnb, *ln2b, *h1b, *wq, *wp, *w1, *w2;
    float *xb;
    cudaGetSymbolAddress((void**)&a1w,   g_a1w);
    cudaGetSymbolAddress((void**)&qkvb,  g_qkv);
    cudaGetSymbolAddress((void**)&attnb, g_attn);
    cudaGetSymbolAddress((void**)&xb,    g_x);
    cudaGetSymbolAddress((void**)&ln2b,  g_ln2);
    cudaGetSymbolAddress((void**)&h1b,   g_h1);
    cudaGetSymbolAddress((void**)&wq,    g_wq);
    cudaGetSymbolAddress((void**)&wp,    g_wp);
    cudaGetSymbolAddress((void**)&w1,    g_w1);
    cudaGetSymbolAddress((void**)&w2,    g_w2);

    cudaFuncSetAttribute(gemm_tc<EPI_NONE>,    cudaFuncAttributeMaxDynamicSharedMemorySize, SMEM_BYTES);
    cudaFuncSetAttribute(gemm_tc<EPI_GELU>,    cudaFuncAttributeMaxDynamicSharedMemorySize, SMEM_BYTES);
    cudaFuncSetAttribute(gemm_tc<EPI_SCATTER>, cudaFuncAttributeMaxDynamicSharedMemorySize, SMEM_BYTES);
    cudaFuncSetAttribute(gemm_tc<EPI_RES>,     cudaFuncAttributeMaxDynamicSharedMemorySize, SMEM_BYTES);

    // 0) convert weights to fp16
    round_kernel<<<(1536 * 512) / 1024, 256>>>(qkv_w, wq, 1536 * 512);
    round_kernel<<<(512  * 512) / 1024, 256>>>(proj_w, wp, 512 * 512);
    round_kernel<<<(2048 * 512) / 1024, 256>>>(fc1_w, w1, 2048 * 512);
    round_kernel<<<(512 * 2048) / 1024, 256>>>(fc2_w, w2, 512 * 2048);

    // 1) LN1 + roll + partition (fp16 out)
    ln_kernel<1><<<MROWS, 128>>>(x1, norm1_g, norm1_b, a1w);

    // 2) QKV projection
    {
        dim3 grid(1536 / 128, MROWS / 128);
        gemm_tc<EPI_NONE><<<grid, 256, SMEM_BYTES>>>(a1w, wq, qkv_b, qkvb, nullptr,
                                                     MROWS, 1536, 512);
    }

    // 3) windowed attention
    attn_kernel<<<B_ * NWIN * NH_, 128>>>(qkvb, rel_tab, attnb);

    // 4) proj + reverse + roll + residual (fp32 out)
    {
        dim3 grid(512 / 128, MROWS / 128);
        gemm_tc<EPI_SCATTER><<<grid, 256, SMEM_BYTES>>>(attnb, wp, proj_b, xb, x1,
                                                        MROWS, 512, 512);
    }

    // 5) LN2 (fp16 out)
    ln_kernel<0><<<MROWS, 128>>>(xb, norm2_g, norm2_b, ln2b);

    // 6) fc1 + exact GELU (fp16 out)
    {
        dim3 grid(2048 / 128, MROWS / 128);
        gemm_tc<EPI_GELU><<<grid, 256, SMEM_BYTES>>>(ln2b, w1, fc1_b, h1b, nullptr,
                                                     MROWS, 2048, 512);
    }

    // 7) fc2 + residual -> out (fp32)
    {
        dim3 grid(512 / 128, MROWS / 128);
        gemm_tc<EPI_RES><<<grid, 256, SMEM_BYTES>>>(h1b, w2, fc2_b, d_out, xb,
                                                    MROWS, 512, 2048);
    }
}

// round 9
// speedup vs baseline: 6.7623x; 1.0817x over previous
#include <cuda_runtime.h>
#include <cuda_fp16.h>
#include <math.h>
#include <stdint.h>

// Problem constants
#define B_    16
#define HH    56
#define WW_   56
#define C_    512
#define NH_   16
#define WS_   7
#define SS_   3
#define NTOK  49
#define NWIN  64
#define HD_   32
#define MLPH  2048
#define MROWS 50176
#define SCALE_ 0.17677669529663687f

// ---------------- scratch ----------------------------------------------------
__device__ __half g_a1w [(size_t)MROWS * 512];
__device__ __half g_qkv [(size_t)MROWS * 1536];
__device__ __half g_attn[(size_t)MROWS * 512];
__device__ float  g_x   [(size_t)MROWS * 512];
__device__ __half g_ln2 [(size_t)MROWS * 512];
__device__ __half g_h1  [(size_t)MROWS * 2048];
__device__ __half g_wq [1536 * 512];
__device__ __half g_wp [512 * 512];
__device__ __half g_w1 [2048 * 512];
__device__ __half g_w2 [512 * 2048];

__global__ __launch_bounds__(256)
void round_kernel(const float* __restrict__ src, __half* __restrict__ dst, int n)
{
    int i = blockIdx.x * 1024 + threadIdx.x * 4;
    if (i < n) {
        float4 v = *(const float4*)(src + i);
        *(__half2*)(dst + i)     = __floats2half2_rn(v.x, v.y);
        *(__half2*)(dst + i + 2) = __floats2half2_rn(v.z, v.w);
    }
}

// ---------------- LayerNorm (fp32 in -> fp16 out) -----------------------------
template <int MODE>
__global__ __launch_bounds__(128)
void ln_kernel(const float* __restrict__ src, const float* __restrict__ g,
               const float* __restrict__ b, __half* __restrict__ dst)
{
    const int m = blockIdx.x;
    const float* row;
    if (MODE == 1) {
        int r  = m / NTOK, nt = m % NTOK;
        int bb = r >> 6,   wi = r & 63;
        int wh = wi >> 3,  ww = wi & 7;
        int ih = nt / 7,   iw = nt % 7;
        int hs = wh * 7 + ih + SS_; if (hs >= HH)  hs -= HH;
        int ws = ww * 7 + iw + SS_; if (ws >= WW_) ws -= WW_;
        row = src + ((size_t)bb * 3136 + hs * 56 + ws) * 512;
    } else {
        row = src + (size_t)m * 512;
    }
    const int t = threadIdx.x;
    float4 v = *(const float4*)(row + t * 4);
    float s = v.x + v.y + v.z + v.w;
    float q = v.x * v.x + v.y * v.y + v.z * v.z + v.w * v.w;
    #pragma unroll
    for (int o = 16; o; o >>= 1) {
        s += __shfl_xor_sync(0xffffffffu, s, o);
        q += __shfl_xor_sync(0xffffffffu, q, o);
    }
    __shared__ float red[8];
    int warp = t >> 5, lane = t & 31;
    if (lane == 0) { red[warp] = s; red[warp + 4] = q; }
    __syncthreads();
    s = red[0] + red[1] + red[2] + red[3];
    q = red[4] + red[5] + red[6] + red[7];
    float mean = s * (1.0f / 512.0f);
    float var  = q * (1.0f / 512.0f) - mean * mean;
    float rstd = rsqrtf(var + 1e-5f);
    float4 gv = *(const float4*)(g + t * 4);
    float4 bv = *(const float4*)(b + t * 4);
    *(__half2*)(dst + (size_t)m * 512 + t * 4) =
        __floats2half2_rn((v.x - mean) * rstd * gv.x + bv.x,
                          (v.y - mean) * rstd * gv.y + bv.y);
    *(__half2*)(dst + (size_t)m * 512 + t * 4 + 2) =
        __floats2half2_rn((v.z - mean) * rstd * gv.z + bv.z,
                          (v.w - mean) * rstd * gv.w + bv.w);
}

// ---------------- fp16 tensor-core GEMM (ldmatrix + 3-stage pipeline) ---------
enum { EPI_NONE = 0, EPI_GELU = 1, EPI_SCATTER = 2, EPI_RES = 3 };

#define LDTH 40                         // pitch in halves (80B)
#define ASZH (128 * LDTH)               // halves per matrix per stage
#define STG_BYTES (2 * ASZH * 2)        // A+B per stage (20480 B)
#define NSTG 3
#define SMEM_BYTES (NSTG * STG_BYTES)

__device__ __forceinline__ void mma16(float* c, const uint32_t* a, uint32_t b0, uint32_t b1) {
    asm volatile(
        "mma.sync.aligned.m16n8k16.row.col.f32.f16.f16.f32 "
        "{%0,%1,%2,%3},{%4,%5,%6,%7},{%8,%9},{%0,%1,%2,%3};\n"
        : "+f"(c[0]), "+f"(c[1]), "+f"(c[2]), "+f"(c[3])
        : "r"(a[0]), "r"(a[1]), "r"(a[2]), "r"(a[3]), "r"(b0), "r"(b1));
}
__device__ __forceinline__ void ldsm4(uint32_t* r, uint32_t addr) {
    asm volatile("ldmatrix.sync.aligned.m8n8.x4.shared.b16 {%0,%1,%2,%3}, [%4];"
        : "=r"(r[0]), "=r"(r[1]), "=r"(r[2]), "=r"(r[3]) : "r"(addr));
}
__device__ __forceinline__ void cp16(uint32_t dst, const void* src) {
    asm volatile("cp.async.cg.shared.global [%0], [%1], 16;\n" :: "r"(dst), "l"(src));
}
__device__ __forceinline__ void cp_commit() { asm volatile("cp.async.commit_group;\n"); }
__device__ __forceinline__ void cp_wait1()  { asm volatile("cp.async.wait_group 1;\n"); }

__device__ __forceinline__ size_t scatter_row(int m) {
    int r  = m / NTOK, nt = m % NTOK;
    int bb = r >> 6,   wi = r & 63;
    int wh = wi >> 3,  ww = wi & 7;
    int ih = nt / 7,   iw = nt % 7;
    int h = wh * 7 + ih + SS_; if (h >= HH)  h -= HH;
    int w = ww * 7 + iw + SS_; if (w >= WW_) w -= WW_;
    return (size_t)bb * 3136 + h * 56 + w;
}

// A [M,K] fp16 row-major, B [N,K] fp16 row-major; C = A @ B^T + bias.
template <int EPI>
__global__ __launch_bounds__(256, 2)
void gemm_tc(const __half* __restrict__ A, const __half* __restrict__ Bw,
             const float* __restrict__ bias, void* __restrict__ Cv,
             const float* __restrict__ res, int M, int N, int K)
{
    extern __shared__ __half sm[];
    const int tid  = threadIdx.x;
    const int lane = tid & 31, warp = tid >> 5;
    const int wm = warp & 1, wn = warp >> 1;          // 2x4 warps, warp tile 64x32
    const int m0 = blockIdx.y * 128, n0 = blockIdx.x * 128;

    float acc[4][4][4];
    #pragma unroll
    for (int i = 0; i < 4; i++)
        #pragma unroll
        for (int j = 0; j < 4; j++)
            #pragma unroll
            for (int t = 0; t < 4; t++) acc[i][j][t] = 0.0f;

    // loader mapping: thread -> one row, 16 halves (2x 16B)
    const int ldRow = tid >> 1;
    const int ldCol = (tid & 1) * 16;
    const __half* aSrc = A  + (size_t)(m0 + ldRow) * K + ldCol;
    const __half* bSrc = Bw + (size_t)(n0 + ldRow) * K + ldCol;
    const uint32_t smBase = (uint32_t)__cvta_generic_to_shared(sm);
    const uint32_t aDst = smBase + (uint32_t)(ldRow * LDTH + ldCol) * 2;
    const uint32_t bDst = aDst + ASZH * 2;

    const int niter = K >> 5;   // BK = 32

    // prologue: stages 0,1
    #pragma unroll
    for (int s = 0; s < 2; s++) {
        const __half* as = aSrc + s * 32;
        const __half* bs = bSrc + s * 32;
        const uint32_t off = s * STG_BYTES;
        cp16(aDst + off,      as);
        cp16(aDst + off + 16, as + 8);
        cp16(bDst + off,      bs);
        cp16(bDst + off + 16, bs + 8);
        cp_commit();
    }

    // ldmatrix per-thread base address (within a stage)
    const int lrow  = lane & 15;
    const int lcol8 = (lane >> 4) * 8;
    const uint32_t aLd = smBase + (uint32_t)((wm * 64 + lrow) * LDTH + lcol8) * 2;
    const uint32_t bLd = smBase + ASZH * 2 + (uint32_t)((wn * 32 + lrow) * LDTH + lcol8) * 2;

    int buf = 0;
    for (int it = 0; it < niter; it++) {
        cp_wait1();
        __syncthreads();

        if (it + 2 < niter) {
            const int nb = (buf + 2 >= NSTG) ? buf + 2 - NSTG : buf + 2;
            const __half* as = aSrc + (it + 2) * 32;
            const __half* bs = bSrc + (it + 2) * 32;
            const uint32_t off = nb * STG_BYTES;
            cp16(aDst + off,      as);
            cp16(aDst + off + 16, as + 8);
            cp16(bDst + off,      bs);
            cp16(bDst + off + 16, bs + 8);
        }
        cp_commit();   // commit every iter (possibly empty) to keep group count in sync

        const uint32_t so = buf * STG_BYTES;
        #pragma unroll
        for (int kk = 0; kk < 32; kk += 16) {
            uint32_t af[4][4], bq[2][4];
            #pragma unroll
            for (int im = 0; im < 4; im++)
                ldsm4(af[im], aLd + so + (uint32_t)(im * 16 * LDTH + kk) * 2);
            #pragma unroll
            for (int p = 0; p < 2; p++)
                ldsm4(bq[p], bLd + so + (uint32_t)(p * 16 * LDTH + kk) * 2);
            #pragma unroll
            for (int im = 0; im < 4; im++)
                #pragma unroll
                for (int jn = 0; jn < 4; jn++)
                    mma16(acc[im][jn], af[im], bq[jn >> 1][jn & 1], bq[jn >> 1][2 + (jn & 1)]);
        }
        buf = (buf + 1 == NSTG) ? 0 : buf + 1;
    }

    // epilogue
    const int row = lane >> 2, col = lane & 3;
    #pragma unroll
    for (int im = 0; im < 4; im++) {
        const int r0 = m0 + wm * 64 + im * 16 + row;
        const int r1 = r0 + 8;
        size_t o0, o1;
        if (EPI == EPI_SCATTER) { o0 = scatter_row(r0); o1 = scatter_row(r1); }
        else                    { o0 = (size_t)r0;      o1 = (size_t)r1; }
        #pragma unroll
        for (int jn = 0; jn < 4; jn++) {
            const int n = n0 + wn * 32 + jn * 8 + 2 * col;
            const float b0 = bias[n], b1 = bias[n + 1];
            float v0 = acc[im][jn][0] + b0, v1 = acc[im][jn][1] + b1;
            float v2 = acc[im][jn][2] + b0, v3 = acc[im][jn][3] + b1;
            if (EPI == EPI_GELU) {
                v0 = 0.5f * v0 * (1.0f + erff(v0 * 0.70710678118654752f));
                v1 = 0.5f * v1 * (1.0f + erff(v1 * 0.70710678118654752f));
                v2 = 0.5f * v2 * (1.0f + erff(v2 * 0.70710678118654752f));
                v3 = 0.5f * v3 * (1.0f + erff(v3 * 0.70710678118654752f));
            }
            if (EPI == EPI_NONE || EPI == EPI_GELU) {
                __half* C = (__half*)Cv;
                *(__half2*)(C + o0 * N + n) = __floats2half2_rn(v0, v1);
                *(__half2*)(C + o1 * N + n) = __floats2half2_rn(v2, v3);
            } else {
                float* C = (float*)Cv;
                v0 += res[o0 * N + n]; v1 += res[o0 * N + n + 1];
                v2 += res[o1 * N + n]; v3 += res[o1 * N + n + 1];
                *(float2*)(C + o0 * N + n) = make_float2(v0, v1);
                *(float2*)(C + o1 * N + n) = make_float2(v2, v3);
            }
        }
    }
}

// ---------------- Windowed attention -----------------------------------------
__global__ __launch_bounds__(128)
void attn_kernel(const __half* __restrict__ qkv, const float* __restrict__ rel_tab,
                 __half* __restrict__ out)
{
    __shared__ float Qs[NTOK][33], Ks[NTOK][33], Vs[NTOK][33];
    __shared__ float S[NTOK * NTOK];

    const int bi = blockIdx.x;
    const int h  = bi & 15;
    const int r  = bi >> 4;
    const int wi = r & 63;
    const int tid = threadIdx.x;

    const __half* base = qkv + (size_t)r * NTOK * 1536 + h * 32;
    for (int e = tid; e < NTOK * 32; e += 128) {
        int n = e >> 5, d = e & 31;
        Qs[n][d] = __half2float(base[n * 1536 + d]) * SCALE_;
        Ks[n][d] = __half2float(base[n * 1536 + 512 + d]);
        Vs[n][d] = __half2float(base[n * 1536 + 1024 + d]);
    }
    __syncthreads();

    const int wh = wi >> 3, ww = wi & 7;
    for (int e = tid; e < NTOK * NTOK; e += 128) {
        int i = e / NTOK, j = e % NTOK;
        float s = 0.0f;
        #pragma unroll
        for (int d = 0; d < 32; d++) s = fmaf(Qs[i][d], Ks[j][d], s);
        int ih = i / 7, iw = i % 7, jh = j / 7, jw = j % 7;
        int ridx = (ih - jh + 6) * 13 + (iw - jw + 6);
        s += rel_tab[ridx * NH_ + h];
        int hi = wh * 7 + ih, wgi = ww * 7 + iw;
        int hj = wh * 7 + jh, wgj = ww * 7 + jw;
        int li = ((hi < 49) ? 0 : (hi < 53) ? 1 : 2) * 3 + ((wgi < 49) ? 0 : (wgi < 53) ? 1 : 2);
        int lj = ((hj < 49) ? 0 : (hj < 53) ? 1 : 2) * 3 + ((wgj < 49) ? 0 : (wgj < 53) ? 1 : 2);
        if (li != lj) s -= 100.0f;
        S[e] = s;
    }
    __syncthreads();

    const int warp = tid >> 5, lane = tid & 31;
    for (int i = warp; i < NTOK; i += 4) {
        float mx = -1e30f;
        for (int j = lane; j < NTOK; j += 32) mx = fmaxf(mx, S[i * NTOK + j]);
        #pragma unroll
        for (int o = 16; o; o >>= 1) mx = fmaxf(mx, __shfl_xor_sync(0xffffffffu, mx, o));
        float sum = 0.0f;
        for (int j = lane; j < NTOK; j += 32) {
            float p = expf(S[i * NTOK + j] - mx);
            S[i * NTOK + j] = p;
            sum += p;
        }
        #pragma unroll
        for (int o = 16; o; o >>= 1) sum += __shfl_xor_sync(0xffffffffu, sum, o);
        float inv = 1.0f / sum;
        for (int j = lane; j < NTOK; j += 32) S[i * NTOK + j] *= inv;
    }
    __syncthreads();

    __half* obase = out + (size_t)r * NTOK * 512 + h * 32;
    for (int e = tid; e < NTOK * 32; e += 128) {
        int i = e >> 5, d = e & 31;
        float acc = 0.0f;
        #pragma unroll
        for (int j = 0; j < NTOK; j++) acc = fmaf(S[i * NTOK + j], Vs[j][d], acc);
        obase[i * 512 + d] = __float2half_rn(acc);
    }
}

// ---------------- launcher ----------------------------------------------------
extern "C" void kernel_launch(void* const* d_in, const int* in_sizes, int n_in,
                              void* d_out, int out_size)
{
    const float* x1      = (const float*)d_in[0];
    const float* norm1_g = (const float*)d_in[2];
    const float* norm1_b = (const float*)d_in[3];
    const float* qkv_w   = (const float*)d_in[4];
    const float* qkv_b   = (const float*)d_in[5];
    const float* rel_tab = (const float*)d_in[6];
    const float* proj_w  = (const float*)d_in[7];
    const float* proj_b  = (const float*)d_in[8];
    const float* norm2_g = (const float*)d_in[9];
    const float* norm2_b = (const float*)d_in[10];
    const float* fc1_w   = (const float*)d_in[11];
    const float* fc1_b   = (const float*)d_in[12];
    const float* fc2_w   = (const float*)d_in[13];
    const float* fc2_b   = (const float*)d_in[14];

    __half *a1w, *qkvb, *attnb, *ln2b, *h1b, *wq, *wp, *w1, *w2;
    float *xb;
    cudaGetSymbolAddress((void**)&a1w,   g_a1w);
    cudaGetSymbolAddress((void**)&qkvb,  g_qkv);
    cudaGetSymbolAddress((void**)&attnb, g_attn);
    cudaGetSymbolAddress((void**)&xb,    g_x);
    cudaGetSymbolAddress((void**)&ln2b,  g_ln2);
    cudaGetSymbolAddress((void**)&h1b,   g_h1);
    cudaGetSymbolAddress((void**)&wq,    g_wq);
    cudaGetSymbolAddress((void**)&wp,    g_wp);
    cudaGetSymbolAddress((void**)&w1,    g_w1);
    cudaGetSymbolAddress((void**)&w2,    g_w2);

    cudaFuncSetAttribute(gemm_tc<EPI_NONE>,    cudaFuncAttributeMaxDynamicSharedMemorySize, SMEM_BYTES);
    cudaFuncSetAttribute(gemm_tc<EPI_GELU>,    cudaFuncAttributeMaxDynamicSharedMemorySize, SMEM_BYTES);
    cudaFuncSetAttribute(gemm_tc<EPI_SCATTER>, cudaFuncAttributeMaxDynamicSharedMemorySize, SMEM_BYTES);
    cudaFuncSetAttribute(gemm_tc<EPI_RES>,     cudaFuncAttributeMaxDynamicSharedMemorySize, SMEM_BYTES);

    // 0) convert weights to fp16
    round_kernel<<<(1536 * 512) / 1024, 256>>>(qkv_w, wq, 1536 * 512);
    round_kernel<<<(512  * 512) / 1024, 256>>>(proj_w, wp, 512 * 512);
    round_kernel<<<(2048 * 512) / 1024, 256>>>(fc1_w, w1, 2048 * 512);
    round_kernel<<<(512 * 2048) / 1024, 256>>>(fc2_w, w2, 512 * 2048);

    // 1) LN1 + roll + partition (fp16 out)
    ln_kernel<1><<<MROWS, 128>>>(x1, norm1_g, norm1_b, a1w);

    // 2) QKV projection
    {
        dim3 grid(1536 / 128, MROWS / 128);
        gemm_tc<EPI_NONE><<<grid, 256, SMEM_BYTES>>>(a1w, wq, qkv_b, qkvb, nullptr,
                                                     MROWS, 1536, 512);
    }

    // 3) windowed attention
    attn_kernel<<<B_ * NWIN * NH_, 128>>>(qkvb, rel_tab, attnb);

    // 4) proj + reverse + roll + residual (fp32 out)
    {
        dim3 grid(512 / 128, MROWS / 128);
        gemm_tc<EPI_SCATTER><<<grid, 256, SMEM_BYTES>>>(attnb, wp, proj_b, xb, x1,
                                                        MROWS, 512, 512);
    }

    // 5) LN2 (fp16 out)
    ln_kernel<0><<<MROWS, 128>>>(xb, norm2_g, norm2_b, ln2b);

    // 6) fc1 + exact GELU (fp16 out)
    {
        dim3 grid(2048 / 128, MROWS / 128);
        gemm_tc<EPI_GELU><<<grid, 256, SMEM_BYTES>>>(ln2b, w1, fc1_b, h1b, nullptr,
                                                     MROWS, 2048, 512);
    }

    // 7) fc2 + residual -> out (fp32)
    {
        dim3 grid(512 / 128, MROWS / 128);
        gemm_tc<EPI_RES><<<grid, 256, SMEM_BYTES>>>(h1b, w2, fc2_b, d_out, xb,
                                                    MROWS, 512, 2048);
    }
}